// round 11
// baseline (speedup 1.0000x reference)
#include <cuda_runtime.h>

// ---------------------------------------------------------------------------
// OmniSuperPointTransformer: gather + pos-MLP (3->32 LN ReLU 32->32) +
// fused segment-mean scatter into superpoints.
//
//  * smean(x)+smean(x_pos) == segsum(x + x_pos)/denom -> ONE accumulator per
//    superpoint: [32 feat | 3 xyz | 1 count] = 36 f32 (7.2 MB, fits L2).
//  * red.global.add.v4.f32: 9 vector REDs per point.
//  * fma.rn.f32x2 packed math: the 32x32 matmul runs as 512 FMA2 instead of
//    1024 FFMA (ptxas never emits FFMA2 from C++; PTX-only).
//  * pre-centered LayerNorm: mu(h) is linear in xyz, so fold it into
//    W1/b1 once per launch -> no mean reduction, no subtracts per point.
//  * random 128B voxel gather issued FIRST, consumed only in the epilogue,
//    so DRAM latency hides under the MLP math.
// ---------------------------------------------------------------------------

#define N_SP_MAX   50000
#define ACC_STRIDE 36
#define LN_EPS     1e-5f

__device__ __align__(16) float g_acc[N_SP_MAX * ACC_STRIDE];
__device__ __align__(16) float g_W1c[96];
__device__ __align__(16) float g_b1c[32];

__global__ void osp_zero_kernel(int n4) {
    int i = blockIdx.x * blockDim.x + threadIdx.x;
    if (i < n4) reinterpret_cast<float4*>(g_acc)[i] = make_float4(0.f, 0.f, 0.f, 0.f);
}

// Center W1/b1 so that Linear(3,32) output is already zero-mean over channels.
__global__ void osp_center_kernel(const float* __restrict__ W1,
                                  const float* __restrict__ b1) {
    __shared__ float m[4];
    int c = threadIdx.x;               // 32 threads
    if (c < 3) {
        float s = 0.f;
        for (int j = 0; j < 32; j++) s += W1[c * 32 + j];
        m[c] = s * (1.f / 32.f);
    } else if (c == 3) {
        float s = 0.f;
        for (int j = 0; j < 32; j++) s += b1[j];
        m[3] = s * (1.f / 32.f);
    }
    __syncthreads();
    g_W1c[0 * 32 + c] = W1[0 * 32 + c] - m[0];
    g_W1c[1 * 32 + c] = W1[1 * 32 + c] - m[1];
    g_W1c[2 * 32 + c] = W1[2 * 32 + c] - m[2];
    g_b1c[c]          = b1[c] - m[3];
}

// ---- packed f32x2 helpers --------------------------------------------------
typedef unsigned long long u64;

__device__ __forceinline__ u64 pack2(float lo, float hi) {
    u64 r; asm("mov.b64 %0, {%1, %2};" : "=l"(r) : "f"(lo), "f"(hi)); return r;
}
__device__ __forceinline__ void unpack2(u64 v, float& lo, float& hi) {
    asm("mov.b64 {%0, %1}, %2;" : "=f"(lo), "=f"(hi) : "l"(v));
}
__device__ __forceinline__ void fma2(u64& d, u64 a, u64 b) {
    asm("fma.rn.f32x2 %0, %1, %2, %0;" : "+l"(d) : "l"(a), "l"(b));
}
__device__ __forceinline__ void add2(u64& d, u64 a) {
    asm("add.rn.f32x2 %0, %0, %1;" : "+l"(d) : "l"(a));
}
__device__ __forceinline__ void lds_v2u64(unsigned sa, u64& a, u64& b) {
    asm("ld.shared.v2.b64 {%0, %1}, [%2];" : "=l"(a), "=l"(b) : "r"(sa));
}
__device__ __forceinline__ void red_add_v4(float* addr, float a, float b, float c, float d) {
    asm volatile("red.global.add.v4.f32 [%0], {%1, %2, %3, %4};"
                 :: "l"(addr), "f"(a), "f"(b), "f"(c), "f"(d) : "memory");
}

// ---------------------------------------------------------------------------
__global__ __launch_bounds__(256)
void osp_point_kernel(const float* __restrict__ voxel_feats,
                      const float* __restrict__ xyz,
                      const float* __restrict__ gamma,
                      const float* __restrict__ beta,
                      const float* __restrict__ W2,
                      const float* __restrict__ b2,
                      const int*   __restrict__ p2v,
                      const int*   __restrict__ spid,
                      int n_points)
{
    __shared__ __align__(16) float sW1[96];
    __shared__ __align__(16) float sb1[32], sg[32], sbt[32], sb2[32];
    __shared__ __align__(16) float sW2[1024];

    for (int t = threadIdx.x; t < 96; t += blockDim.x) sW1[t] = g_W1c[t];
    if (threadIdx.x < 32) {
        sb1[threadIdx.x] = g_b1c[threadIdx.x];
        sg [threadIdx.x] = gamma[threadIdx.x];
        sbt[threadIdx.x] = beta[threadIdx.x];
        sb2[threadIdx.x] = b2[threadIdx.x];
    }
    for (int t = threadIdx.x; t < 1024; t += blockDim.x) sW2[t] = W2[t];
    __syncthreads();

    int i = blockIdx.x * blockDim.x + threadIdx.x;
    if (i >= n_points) return;

    // ---- random gather issued first; consumed only in the epilogue -------
    int v  = p2v[i];
    int sp = spid[i];
    const ulonglong2* vf = reinterpret_cast<const ulonglong2*>(voxel_feats + (size_t)v * 32);
    u64 g2[16];
#pragma unroll
    for (int j = 0; j < 8; j++) {
        ulonglong2 t = __ldg(vf + j);
        g2[2 * j]     = t.x;
        g2[2 * j + 1] = t.y;
    }

    float px = xyz[3 * i + 0];
    float py = xyz[3 * i + 1];
    float pz = xyz[3 * i + 2];

    unsigned aW1 = (unsigned)__cvta_generic_to_shared(sW1);
    unsigned ab1 = (unsigned)__cvta_generic_to_shared(sb1);
    unsigned aW2 = (unsigned)__cvta_generic_to_shared(sW2);
    unsigned ab2 = (unsigned)__cvta_generic_to_shared(sb2);

    // ---- Linear(3,32) with pre-centered weights: h is zero-mean ----------
    u64 px2 = pack2(px, px), py2 = pack2(py, py), pz2 = pack2(pz, pz);
    u64 h2[16];
#pragma unroll
    for (int j = 0; j < 8; j++) {            // 2 f32x2 pairs per iter
        u64 bA, bB, wA, wB;
        lds_v2u64(ab1 + j * 16, bA, bB);
        h2[2 * j] = bA;  h2[2 * j + 1] = bB;
        lds_v2u64(aW1 + j * 16, wA, wB);            // row 0 (x)
        fma2(h2[2 * j], px2, wA); fma2(h2[2 * j + 1], px2, wB);
        lds_v2u64(aW1 + 128 + j * 16, wA, wB);      // row 1 (y)
        fma2(h2[2 * j], py2, wA); fma2(h2[2 * j + 1], py2, wB);
        lds_v2u64(aW1 + 256 + j * 16, wA, wB);      // row 2 (z)
        fma2(h2[2 * j], pz2, wA); fma2(h2[2 * j + 1], pz2, wB);
    }

    // ---- LayerNorm (h already centered) + ReLU ----------------------------
    float h[32];
#pragma unroll
    for (int j = 0; j < 16; j++) unpack2(h2[j], h[2 * j], h[2 * j + 1]);

    float var = 0.f;
#pragma unroll
    for (int c = 0; c < 32; c++) var = fmaf(h[c], h[c], var);
    var *= (1.f / 32.f);
    float inv = rsqrtf(var + LN_EPS);
#pragma unroll
    for (int c = 0; c < 32; c++) {
        float t = fmaf(h[c] * inv, sg[c], sbt[c]);
        h[c] = fmaxf(t, 0.f);
    }

    // ---- Linear(32,32), packed: o[c] = sum_k h[k]*W2[k][c] + b2[c] --------
    u64 o2[16];
#pragma unroll
    for (int j = 0; j < 8; j++) lds_v2u64(ab2 + j * 16, o2[2 * j], o2[2 * j + 1]);

#pragma unroll
    for (int k = 0; k < 32; k++) {
        u64 a2 = pack2(h[k], h[k]);
        unsigned rowa = aW2 + k * 128;
#pragma unroll
        for (int j = 0; j < 8; j++) {
            u64 wA, wB;
            lds_v2u64(rowa + j * 16, wA, wB);
            fma2(o2[2 * j],     a2, wA);
            fma2(o2[2 * j + 1], a2, wB);
        }
    }

    // ---- fold gathered voxel feats in (packed adds), then scatter ---------
#pragma unroll
    for (int j = 0; j < 16; j++) add2(o2[j], g2[j]);

    float* base = g_acc + (size_t)sp * ACC_STRIDE;
#pragma unroll
    for (int j = 0; j < 8; j++) {
        float f0, f1, f2v, f3;
        unpack2(o2[2 * j],     f0, f1);
        unpack2(o2[2 * j + 1], f2v, f3);
        red_add_v4(base + j * 4, f0, f1, f2v, f3);
    }
    red_add_v4(base + 32, px, py, pz, 1.0f);
}

// ---------------------------------------------------------------------------
__global__ void osp_finalize_kernel(float* __restrict__ out, int S) {
    int idx = blockIdx.x * blockDim.x + threadIdx.x;
    int total = S * 35;
    if (idx >= total) return;

    int featN = S * 32;
    int sp, col;
    if (idx < featN) { sp = idx >> 5; col = idx & 31; }
    else { int r = idx - featN; sp = r / 3; col = 32 + r % 3; }

    const float* base = g_acc + (size_t)sp * ACC_STRIDE;
    float den = fmaxf(base[35], 1.0f);
    out[idx] = base[col] / den;
}

// ---------------------------------------------------------------------------
extern "C" void kernel_launch(void* const* d_in, const int* in_sizes, int n_in,
                              void* d_out, int out_size)
{
    const float* voxel_feats = (const float*)d_in[0];
    const float* xyz         = (const float*)d_in[1];
    const float* W1          = (const float*)d_in[2];
    const float* b1          = (const float*)d_in[3];
    const float* gamma       = (const float*)d_in[4];
    const float* beta        = (const float*)d_in[5];
    const float* W2          = (const float*)d_in[6];
    const float* b2          = (const float*)d_in[7];
    const int*   p2v         = (const int*)d_in[8];
    const int*   spid        = (const int*)d_in[9];

    int n_points = in_sizes[8];
    int S        = out_size / 35;
    if (S > N_SP_MAX) S = N_SP_MAX;

    int n4 = (S * ACC_STRIDE) / 4;
    osp_zero_kernel<<<(n4 + 255) / 256, 256>>>(n4);
    osp_center_kernel<<<1, 32>>>(W1, b1);

    osp_point_kernel<<<(n_points + 255) / 256, 256>>>(
        voxel_feats, xyz, gamma, beta, W2, b2, p2v, spid, n_points);

    int total = S * 35;
    osp_finalize_kernel<<<(total + 255) / 256, 256>>>((float*)d_out, S);
}

// round 12
// speedup vs baseline: 1.2452x; 1.2452x over previous
#include <cuda_runtime.h>

// ---------------------------------------------------------------------------
// OmniSuperPointTransformer: gather + pos-MLP (3->32 LN ReLU 32->32) +
// fused segment-mean scatter into superpoints.
//
// Core algebra:
//  * smean(x)+smean(x_pos) == [segsum(x) + segsum(ReLU(h))@W2 + count*b2]/den
//    -> the 32x32 matmul COMMUTES with the segment sum: apply it once per
//       superpoint (50K x 1024 FMA ~ 3us) instead of once per point
//       (2M x 1024 FMA ~ 130us).  Per-point math is just Linear(3,32)+LN+ReLU.
//  * accumulator per superpoint: [32 feat | 32 reluH | 3 xyz | 1 count]
//    = 68 f32 -> 13.6 MB, fits L2 -> REDs resolve at LTS.
//  * red.global.add.v4.f32 (no-return vector reduction): 17 v4 per point.
//  * pre-centered LayerNorm: mean(h) is linear in xyz -> folded into W1/b1
//    once per launch; no mean reduction per point.
//  * random 128B voxel gather issued FIRST, consumed only in the epilogue.
// ---------------------------------------------------------------------------

#define N_SP_MAX   50000
#define ACC_STRIDE 68        // 32 feat | 32 reluH | 3 xyz | 1 count (272B row)
#define LN_EPS     1e-5f

__device__ __align__(16) float g_acc[N_SP_MAX * ACC_STRIDE];
__device__ __align__(16) float g_W1c[96];
__device__ __align__(16) float g_b1c[32];

__global__ void osp_zero_kernel(int n4) {
    int i = blockIdx.x * blockDim.x + threadIdx.x;
    if (i < n4) reinterpret_cast<float4*>(g_acc)[i] = make_float4(0.f, 0.f, 0.f, 0.f);
}

// Center W1/b1 so that Linear(3,32) output is already zero-mean over channels.
__global__ void osp_center_kernel(const float* __restrict__ W1,
                                  const float* __restrict__ b1) {
    __shared__ float m[4];
    int c = threadIdx.x;               // 32 threads
    if (c < 3) {
        float s = 0.f;
        for (int j = 0; j < 32; j++) s += W1[c * 32 + j];
        m[c] = s * (1.f / 32.f);
    } else if (c == 3) {
        float s = 0.f;
        for (int j = 0; j < 32; j++) s += b1[j];
        m[3] = s * (1.f / 32.f);
    }
    __syncthreads();
    g_W1c[0 * 32 + c] = W1[0 * 32 + c] - m[0];
    g_W1c[1 * 32 + c] = W1[1 * 32 + c] - m[1];
    g_W1c[2 * 32 + c] = W1[2 * 32 + c] - m[2];
    g_b1c[c]          = b1[c] - m[3];
}

__device__ __forceinline__ void red_add_v4(float* addr, float a, float b, float c, float d) {
    asm volatile("red.global.add.v4.f32 [%0], {%1, %2, %3, %4};"
                 :: "l"(addr), "f"(a), "f"(b), "f"(c), "f"(d) : "memory");
}

// ---------------------------------------------------------------------------
// Per-point: gather voxel row, Linear(3,32)+LN+ReLU, scatter 17 x red.v4.
__global__ __launch_bounds__(256)
void osp_point_kernel(const float* __restrict__ voxel_feats,
                      const float* __restrict__ xyz,
                      const float* __restrict__ gamma,
                      const float* __restrict__ beta,
                      const int*   __restrict__ p2v,
                      const int*   __restrict__ spid,
                      int n_points)
{
    __shared__ __align__(16) float sW1[96];
    __shared__ __align__(16) float sb1[32], sg[32], sbt[32];

    for (int t = threadIdx.x; t < 96; t += blockDim.x) sW1[t] = g_W1c[t];
    if (threadIdx.x < 32) {
        sb1[threadIdx.x] = g_b1c[threadIdx.x];
        sg [threadIdx.x] = gamma[threadIdx.x];
        sbt[threadIdx.x] = beta[threadIdx.x];
    }
    __syncthreads();

    int i = blockIdx.x * blockDim.x + threadIdx.x;
    if (i >= n_points) return;

    // random gather issued first; consumed only at the scatter
    int v  = p2v[i];
    int sp = spid[i];
    const float4* vf = reinterpret_cast<const float4*>(voxel_feats + (size_t)v * 32);
    float4 gth[8];
#pragma unroll
    for (int j = 0; j < 8; j++) gth[j] = __ldg(vf + j);

    float px = xyz[3 * i + 0];
    float py = xyz[3 * i + 1];
    float pz = xyz[3 * i + 2];

    // Linear(3,32) with pre-centered weights -> h is zero-mean over channels
    float h[32];
    float var = 0.f;
#pragma unroll
    for (int c = 0; c < 32; c++) {
        float t = fmaf(px, sW1[c], fmaf(py, sW1[32 + c], fmaf(pz, sW1[64 + c], sb1[c])));
        h[c] = t;
        var = fmaf(t, t, var);
    }
    var *= (1.f / 32.f);
    float inv = rsqrtf(var + LN_EPS);
#pragma unroll
    for (int c = 0; c < 32; c++) {
        float t = fmaf(h[c] * inv, sg[c], sbt[c]);
        h[c] = fmaxf(t, 0.f);          // ReLU(h): accumulated pre-W2
    }

    float* base = g_acc + (size_t)sp * ACC_STRIDE;
#pragma unroll
    for (int j = 0; j < 8; j++)
        red_add_v4(base + 4 * j, gth[j].x, gth[j].y, gth[j].z, gth[j].w);
#pragma unroll
    for (int j = 0; j < 8; j++)
        red_add_v4(base + 32 + 4 * j, h[4 * j], h[4 * j + 1], h[4 * j + 2], h[4 * j + 3]);
    red_add_v4(base + 64, px, py, pz, 1.0f);
}

// ---------------------------------------------------------------------------
// Per-superpoint: out = (accF + accReluH @ W2 + cnt*b2) / den ; xyz /= den.
// out layout: [S*32 feat | S*3 xyz].
__global__ __launch_bounds__(256)
void osp_finalize_kernel(float* __restrict__ out,
                         const float* __restrict__ W2,
                         const float* __restrict__ b2,
                         int S)
{
    __shared__ __align__(16) float sW2[1024];
    __shared__ __align__(16) float sb2[32];
    for (int t = threadIdx.x; t < 1024; t += blockDim.x) sW2[t] = W2[t];
    if (threadIdx.x < 32) sb2[threadIdx.x] = b2[threadIdx.x];
    __syncthreads();

    int sp = blockIdx.x * blockDim.x + threadIdx.x;
    if (sp >= S) return;

    const float* base = g_acc + (size_t)sp * ACC_STRIDE;

    float cnt = base[67];
    float den = fmaxf(cnt, 1.0f);
    float rinv = 1.0f / den;

    float rh[32];
#pragma unroll
    for (int j = 0; j < 8; j++) {
        float4 t = reinterpret_cast<const float4*>(base + 32)[j];
        rh[4 * j] = t.x; rh[4 * j + 1] = t.y; rh[4 * j + 2] = t.z; rh[4 * j + 3] = t.w;
    }

    float o[32];
#pragma unroll
    for (int c = 0; c < 32; c++) o[c] = fmaf(cnt, sb2[c], base[c]);  // accF + cnt*b2

#pragma unroll
    for (int k = 0; k < 32; k++) {
        float a = rh[k];
        const float* wr = sW2 + k * 32;
#pragma unroll
        for (int c = 0; c < 32; c++) o[c] = fmaf(a, wr[c], o[c]);
    }

    float4* od = reinterpret_cast<float4*>(out + (size_t)sp * 32);
#pragma unroll
    for (int j = 0; j < 8; j++) {
        float4 t;
        t.x = o[4 * j]     * rinv;
        t.y = o[4 * j + 1] * rinv;
        t.z = o[4 * j + 2] * rinv;
        t.w = o[4 * j + 3] * rinv;
        od[j] = t;
    }

    float* ox = out + (size_t)S * 32 + (size_t)sp * 3;
    ox[0] = base[64] * rinv;
    ox[1] = base[65] * rinv;
    ox[2] = base[66] * rinv;
}

// ---------------------------------------------------------------------------
extern "C" void kernel_launch(void* const* d_in, const int* in_sizes, int n_in,
                              void* d_out, int out_size)
{
    const float* voxel_feats = (const float*)d_in[0];
    const float* xyz         = (const float*)d_in[1];
    const float* W1          = (const float*)d_in[2];
    const float* b1          = (const float*)d_in[3];
    const float* gamma       = (const float*)d_in[4];
    const float* beta        = (const float*)d_in[5];
    const float* W2          = (const float*)d_in[6];
    const float* b2          = (const float*)d_in[7];
    const int*   p2v         = (const int*)d_in[8];
    const int*   spid        = (const int*)d_in[9];

    int n_points = in_sizes[8];
    int S        = out_size / 35;
    if (S > N_SP_MAX) S = N_SP_MAX;

    int n4 = (S * ACC_STRIDE) / 4;       // 68 % 4 == 0
    osp_zero_kernel<<<(n4 + 255) / 256, 256>>>(n4);
    osp_center_kernel<<<1, 32>>>(W1, b1);

    osp_point_kernel<<<(n_points + 255) / 256, 256>>>(
        voxel_feats, xyz, gamma, beta, p2v, spid, n_points);

    osp_finalize_kernel<<<(S + 255) / 256, 256>>>((float*)d_out, W2, b2, S);
}

// round 13
// speedup vs baseline: 1.5531x; 1.2473x over previous
#include <cuda_runtime.h>

// ---------------------------------------------------------------------------
// OmniSuperPointTransformer: gather + pos-MLP (3->32 LN ReLU 32->32) +
// fused segment-mean scatter into superpoints.
//
//  * W2 commutes with segment-sum: matmul runs once per superpoint in
//    finalize, not once per point.
//  * WARP-COOPERATIVE point processing (lane = channel):
//      - voxel gather is one coalesced 128B line per point (1 L1tex
//        wavefront instead of 32)
//      - scatter row interleaved [f0,r0,f1,r1,...] so one red.add.v2.f32
//        per lane covers a contiguous 256B row (~2 wavefronts instead of 544
//        per 32 points). Previous thread-per-point kernel was L1tex-
//        wavefront bound (~50M wavefronts); this cuts them ~8x.
//  * pre-centered LayerNorm: mean(h) folded into W1/b1 once per launch.
//  * accumulator: [64 interleaved | x y z cnt] = 68 f32/sp -> 13.6MB, in L2.
// ---------------------------------------------------------------------------

#define N_SP_MAX   50000
#define ACC_STRIDE 68
#define LN_EPS     1e-5f
#define FULLMASK   0xffffffffu

__device__ __align__(16) float g_acc[N_SP_MAX * ACC_STRIDE];
__device__ __align__(16) float g_W1c[96];
__device__ __align__(16) float g_b1c[32];

__global__ void osp_zero_kernel(int n4) {
    int i = blockIdx.x * blockDim.x + threadIdx.x;
    if (i < n4) reinterpret_cast<float4*>(g_acc)[i] = make_float4(0.f, 0.f, 0.f, 0.f);
}

// Center W1/b1 so Linear(3,32) output is zero-mean over channels (exact algebra).
__global__ void osp_center_kernel(const float* __restrict__ W1,
                                  const float* __restrict__ b1) {
    __shared__ float m[4];
    int c = threadIdx.x;               // 32 threads
    if (c < 3) {
        float s = 0.f;
        for (int j = 0; j < 32; j++) s += W1[c * 32 + j];
        m[c] = s * (1.f / 32.f);
    } else if (c == 3) {
        float s = 0.f;
        for (int j = 0; j < 32; j++) s += b1[j];
        m[3] = s * (1.f / 32.f);
    }
    __syncthreads();
    g_W1c[0 * 32 + c] = W1[0 * 32 + c] - m[0];
    g_W1c[1 * 32 + c] = W1[1 * 32 + c] - m[1];
    g_W1c[2 * 32 + c] = W1[2 * 32 + c] - m[2];
    g_b1c[c]          = b1[c] - m[3];
}

__device__ __forceinline__ void red_add_v2(float* addr, float a, float b) {
    asm volatile("red.global.add.v2.f32 [%0], {%1, %2};"
                 :: "l"(addr), "f"(a), "f"(b) : "memory");
}
__device__ __forceinline__ void red_add_v4(float* addr, float a, float b, float c, float d) {
    asm volatile("red.global.add.v4.f32 [%0], {%1, %2, %3, %4};"
                 :: "l"(addr), "f"(a), "f"(b), "f"(c), "f"(d) : "memory");
}

// ---------------------------------------------------------------------------
// One WARP processes 32 consecutive points; lane = channel.
__global__ __launch_bounds__(256)
void osp_point_kernel(const float* __restrict__ voxel_feats,
                      const float* __restrict__ xyz,
                      const float* __restrict__ gamma,
                      const float* __restrict__ beta,
                      const int*   __restrict__ p2v,
                      const int*   __restrict__ spid,
                      int n_points)
{
    int lane = threadIdx.x & 31;
    int warp = blockIdx.x * (blockDim.x >> 5) + (threadIdx.x >> 5);
    long long pbase = (long long)warp * 32;
    if (pbase >= n_points) return;

    // per-lane channel parameters (stay in registers for the whole kernel)
    float w1x = g_W1c[lane], w1y = g_W1c[32 + lane], w1z = g_W1c[64 + lane];
    float b1c = g_b1c[lane];
    float gc  = gamma[lane], btc = beta[lane];

    bool full = (pbase + 32 <= (long long)n_points);
    int nIter = full ? 32 : (int)((long long)n_points - pbase);

    // coalesced preload of this warp's 32 points: indices + xyz (96 floats)
    int pi = (int)pbase + lane;
    int v_l = 0, sp_l = 0;
    float x0 = 0.f, x1 = 0.f, x2 = 0.f;
    if (full) {
        v_l  = p2v[pi];
        sp_l = spid[pi];
        const float* xb = xyz + pbase * 3;
        x0 = xb[lane]; x1 = xb[32 + lane]; x2 = xb[64 + lane];
    } else {
        if (lane < nIter) { v_l = p2v[pi]; sp_l = spid[pi]; }
        int xn = nIter * 3;
        const float* xb = xyz + pbase * 3;
        if (lane      < xn) x0 = xb[lane];
        if (32 + lane < xn) x1 = xb[32 + lane];
        if (64 + lane < xn) x2 = xb[64 + lane];
    }

#pragma unroll 4
    for (int t = 0; t < 32; t++) {
        if (t >= nIter) break;

        int v  = __shfl_sync(FULLMASK, v_l,  t);
        int sp = __shfl_sync(FULLMASK, sp_l, t);

        int ix = 3 * t;            // xyz element indices 3t, 3t+1, 3t+2
        float px = __shfl_sync(FULLMASK, (ix      < 32) ? x0 : ((ix      < 64) ? x1 : x2), ix      & 31);
        float py = __shfl_sync(FULLMASK, (ix + 1  < 32) ? x0 : ((ix + 1  < 64) ? x1 : x2), (ix + 1) & 31);
        float pz = __shfl_sync(FULLMASK, (ix + 2  < 32) ? x0 : ((ix + 2  < 64) ? x1 : x2), (ix + 2) & 31);

        // coalesced gather: one 128B line for this point's voxel row
        float fc = __ldg(voxel_feats + (size_t)v * 32 + lane);

        // Linear(3,32) (pre-centered -> h zero-mean), LN variance via butterfly
        float h = fmaf(px, w1x, fmaf(py, w1y, fmaf(pz, w1z, b1c)));
        float s = h * h;
#pragma unroll
        for (int o = 16; o; o >>= 1) s += __shfl_xor_sync(FULLMASK, s, o);
        float inv = rsqrtf(s * (1.f / 32.f) + LN_EPS);
        float r = fmaxf(fmaf(h * inv, gc, btc), 0.f);

        // coalesced scatter: lane c -> 8B at base+8c (contiguous 256B row)
        float* base = g_acc + (size_t)sp * ACC_STRIDE;
        red_add_v2(base + 2 * lane, fc, r);
        if (lane == 0) red_add_v4(base + 64, px, py, pz, 1.0f);
    }
}

// ---------------------------------------------------------------------------
// One WARP per superpoint: o[c] = (accF[c] + sum_k accR[k]*W2[k][c] + cnt*b2[c]) / den
__global__ __launch_bounds__(256)
void osp_finalize_kernel(float* __restrict__ out,
                         const float* __restrict__ W2,
                         const float* __restrict__ b2,
                         int S)
{
    __shared__ __align__(16) float sW2[1024];
    for (int t = threadIdx.x; t < 1024; t += blockDim.x) sW2[t] = W2[t];
    __syncthreads();

    int lane = threadIdx.x & 31;
    int sp = blockIdx.x * (blockDim.x >> 5) + (threadIdx.x >> 5);
    if (sp >= S) return;

    const float* base = g_acc + (size_t)sp * ACC_STRIDE;
    float2 fr = reinterpret_cast<const float2*>(base)[lane];   // (feat_c, relu_c)
    float cnt = base[67];                                      // broadcast load
    float den = fmaxf(cnt, 1.0f);
    float rinv = 1.0f / den;

    float o = fmaf(cnt, b2[lane], fr.x);
    float r = fr.y;
#pragma unroll
    for (int k = 0; k < 32; k++) {
        float a = __shfl_sync(FULLMASK, r, k);
        o = fmaf(a, sW2[k * 32 + lane], o);
    }

    out[(size_t)sp * 32 + lane] = o * rinv;
    if (lane < 3)
        out[(size_t)S * 32 + (size_t)sp * 3 + lane] = base[64 + lane] * rinv;
}

// ---------------------------------------------------------------------------
extern "C" void kernel_launch(void* const* d_in, const int* in_sizes, int n_in,
                              void* d_out, int out_size)
{
    const float* voxel_feats = (const float*)d_in[0];
    const float* xyz         = (const float*)d_in[1];
    const float* W1          = (const float*)d_in[2];
    const float* b1          = (const float*)d_in[3];
    const float* gamma       = (const float*)d_in[4];
    const float* beta        = (const float*)d_in[5];
    const float* W2          = (const float*)d_in[6];
    const float* b2          = (const float*)d_in[7];
    const int*   p2v         = (const int*)d_in[8];
    const int*   spid        = (const int*)d_in[9];

    int n_points = in_sizes[8];
    int S        = out_size / 35;
    if (S > N_SP_MAX) S = N_SP_MAX;

    int n4 = (S * ACC_STRIDE) / 4;       // 68 % 4 == 0
    osp_zero_kernel<<<(n4 + 255) / 256, 256>>>(n4);
    osp_center_kernel<<<1, 32>>>(W1, b1);

    int warps = (n_points + 31) / 32;            // one warp per 32 points
    int blocks = (warps + 7) / 8;                // 8 warps per 256-thread block
    osp_point_kernel<<<blocks, 256>>>(
        voxel_feats, xyz, gamma, beta, p2v, spid, n_points);

    int fblocks = (S + 7) / 8;                   // one warp per superpoint
    osp_finalize_kernel<<<fblocks, 256>>>((float*)d_out, W2, b2, S);
}